// round 6
// baseline (speedup 1.0000x reference)
#include <cuda_runtime.h>
#include <cstdint>
#include <math.h>

#define N_IMG   4
#define N_ANCH  76725
#define N_CLS   80
#define PRE     512
#define CAND_MAX 2048
#define MAXPC   100
#define MAXD    100

// logit(0.91): s > 0.91 <=> x > 2.3136168
#define XTHR 2.3136168f

#define SEL_SMEM 35072
// k_nms2 smem: sxy@0 8K, sxyw@8192 8K, ssc@16384 2K, sar@18432 2K, mask@20480 32K, scal@53248
#define NMS2_SMEM 53312
#define MRG_SMEM 18688

// ---------------- scratch ----------------
__device__ float4 g_boxes[(size_t)N_IMG * N_ANCH];
__device__ unsigned long long g_cand[(size_t)N_IMG * N_CLS * CAND_MAX];
__device__ uint32_t g_cnt[N_IMG * N_CLS];        // zero-init at load; k_merge re-zeros each launch
__device__ float  g_ts[N_IMG * N_CLS * PRE];
__device__ float4 g_tb[N_IMG * N_CLS * PRE];
__device__ float4 g_te[N_IMG * N_CLS * PRE];
__device__ float  g_cls_scores[N_IMG * N_CLS * MAXPC];
__device__ float4 g_cls_boxes [N_IMG * N_CLS * MAXPC];

// ---------------- kernel 1: streaming candidate select + box decode ----------------
__global__ __launch_bounds__(256) void k_prep(const float* __restrict__ pred) {
    const int TOTV = N_IMG * N_ANCH * 21;
    int g = blockIdx.x * 256 + threadIdx.x;
    if (g >= TOTV) return;
    float4 v = ((const float4*)pred)[g];

    int img = g / (N_ANCH * 21);
    int rem = g - img * (N_ANCH * 21);
    int a   = rem / 21;
    int q   = rem - a * 21;

    if (q == 0) {
        int off, fw, stride;
        if      (a < 57600) { off = 0;     fw = 80; stride = 8;   }
        else if (a < 72000) { off = 57600; fw = 40; stride = 16;  }
        else if (a < 75600) { off = 72000; fw = 20; stride = 32;  }
        else if (a < 76500) { off = 75600; fw = 10; stride = 64;  }
        else                { off = 76500; fw = 5;  stride = 128; }
        int rem2 = a - off;
        int cell = rem2 / 9, k = rem2 - cell * 9;
        int iy = cell / fw, ix = cell - iy * fw;
        float sf    = (float)stride;
        float area  = 16.0f * sf * sf;
        float ratio = (k < 3) ? 0.5f : ((k < 6) ? 1.0f : 2.0f);
        int   si    = k % 3;
        float scale = (si == 0) ? 1.0f : ((si == 1) ? 1.2599210498948732f : 1.5874010519681994f);
        float hh = sqrtf(area / ratio);
        float ww = area / hh;
        float cx = (ix + 0.5f) * sf;
        float cy = (iy + 0.5f) * sf;
        float aw = scale * ww, ah = scale * hh;
        float4 b;
        b.x = v.x * 0.1f * aw + cx;
        b.y = v.y * 0.1f * ah + cy;
        b.z = __expf(v.z * 0.2f) * aw;
        b.w = __expf(v.w * 0.2f) * ah;
        g_boxes[(size_t)img * N_ANCH + a] = b;
    } else {
        float xs[4] = {v.x, v.y, v.z, v.w};
        #pragma unroll
        for (int j = 0; j < 4; j++) {
            float x = xs[j];
            if (x > XTHR) {
                int cls = 4 * q + j - 4;
                float s = __fdividef(1.0f, 1.0f + __expf(-x));
                uint32_t mono = __float_as_uint(s) | 0x80000000u;
                int list = img * N_CLS + cls;
                uint32_t idx = atomicAdd(&g_cnt[list], 1u);
                if (idx < CAND_MAX)
                    g_cand[(size_t)list * CAND_MAX + idx] =
                        ((unsigned long long)mono << 32) | (uint32_t)(~(uint32_t)a);
            }
        }
    }
}

__device__ __forceinline__ void suffix_scan_512(uint32_t v, uint32_t* sufp,
                                                uint32_t* wsum, uint32_t* wsuf, int tid) {
    int lane = tid & 31, wid = tid >> 5;
    uint32_t incl = v;
    #pragma unroll
    for (int d = 1; d < 32; d <<= 1) {
        uint32_t n = __shfl_down_sync(0xFFFFFFFFu, incl, d);
        if (lane + d < 32) incl += n;
    }
    if (lane == 0) wsum[wid] = incl;
    __syncthreads();
    if (tid < 16) {
        uint32_t x = wsum[tid];
        #pragma unroll
        for (int d = 1; d < 16; d <<= 1) {
            uint32_t n = __shfl_down_sync(0x0000FFFFu, x, d);
            if (tid + d < 16) x += n;
        }
        wsuf[tid] = x;
    }
    __syncthreads();
    uint32_t below = (wid < 15) ? wsuf[wid + 1] : 0u;
    sufp[tid] = incl + below;
    if (tid == 0) sufp[512] = 0;
    __syncthreads();
}

__device__ __forceinline__ void agg_hist_add(uint32_t* hist, uint32_t bin, bool active) {
    uint32_t amask = __ballot_sync(0xFFFFFFFFu, active);
    if (!active) return;
    uint32_t peers  = __match_any_sync(amask, bin);
    int      leader = __ffs(peers) - 1;
    if ((threadIdx.x & 31) == leader) atomicAdd(&hist[bin], (uint32_t)__popc(peers));
}

// ---------------- kernel 2a: per (img,class) top-512 select + sort ----------------
__global__ __launch_bounds__(512) void k_select(const float* __restrict__ pred) {
    extern __shared__ char smem[];
    uint32_t* hist = (uint32_t*)smem;
    unsigned long long* keys = (unsigned long long*)smem;
    uint32_t* sufp = (uint32_t*)(smem + 32768);
    uint32_t* wsum = (uint32_t*)(smem + 34824);
    uint32_t* wsuf = (uint32_t*)(smem + 34888);
    uint32_t* scal = (uint32_t*)(smem + 34952);

    int tid = threadIdx.x;
    int bid = blockIdx.x;
    int img = bid / N_CLS;
    int cls = bid - img * N_CLS;

    uint32_t cnt = g_cnt[bid];
    int SORTN;

    if (cnt >= PRE && cnt <= CAND_MAX) {
        SORTN = (cnt <= 1024) ? 1024 : CAND_MAX;
        const unsigned long long* src = &g_cand[(size_t)bid * CAND_MAX];
        for (int i = tid; i < SORTN; i += 512)
            keys[i] = (i < (int)cnt) ? src[i] : 0ull;
        __syncthreads();
    } else {
        SORTN = CAND_MAX;
        for (int i = tid; i < 8192; i += 512) hist[i] = 0;
        __syncthreads();
        for (int a = tid; a < N_ANCH; a += 512) {
            float x = pred[((size_t)img * N_ANCH + a) * 84 + 4 + cls];
            float s = __fdividef(1.0f, 1.0f + __expf(-x));
            uint32_t m = __float_as_uint(s) | 0x80000000u;
            agg_hist_add(hist, m >> 19, true);
        }
        __syncthreads();
        uint32_t v = 0;
        #pragma unroll
        for (int b = 0; b < 16; b++) v += hist[tid * 16 + ((b + tid) & 15)];
        suffix_scan_512(v, sufp, wsum, wsuf, tid);
        {
            uint32_t cur = sufp[tid], nxt = sufp[tid + 1];
            if (cur >= PRE && nxt < PRE) {
                uint32_t run = nxt;
                int T = tid * 16;
                for (int b = 15; b >= 0; b--) {
                    run += hist[tid * 16 + b];
                    if (run >= PRE) { T = tid * 16 + b; break; }
                }
                scal[0] = (uint32_t)T << 19;
            }
            if (tid == 0) scal[3] = 0;
        }
        __syncthreads();
        uint32_t thr = scal[0];
        __syncthreads();
        for (int i = tid; i < CAND_MAX; i += 512) keys[i] = 0ull;
        __syncthreads();
        for (int a = tid; a < N_ANCH; a += 512) {
            float x = pred[((size_t)img * N_ANCH + a) * 84 + 4 + cls];
            float s = __fdividef(1.0f, 1.0f + __expf(-x));
            uint32_t m = __float_as_uint(s) | 0x80000000u;
            if (m >= thr) {
                uint32_t p = atomicAdd(&scal[3], 1u);
                if (p < CAND_MAX)
                    keys[p] = ((unsigned long long)m << 32) | (uint32_t)(~(uint32_t)a);
            }
        }
        __syncthreads();
    }

    for (int k = 2; k <= SORTN; k <<= 1) {
        for (int j = k >> 1; j > 0; j >>= 1) {
            for (int i = tid; i < SORTN; i += 512) {
                int l = i ^ j;
                if (l > i) {
                    unsigned long long x = keys[i], y = keys[l];
                    bool up = ((i & k) == 0);
                    if (up ? (x > y) : (x < y)) { keys[i] = y; keys[l] = x; }
                }
            }
            __syncthreads();
        }
    }

    {
        unsigned long long key = keys[SORTN - 1 - tid];
        uint32_t a = ~((uint32_t)key);
        uint32_t m = (uint32_t)(key >> 32);
        float s = __uint_as_float(m ^ 0x80000000u);
        float4 b = g_boxes[(size_t)img * N_ANCH + a];
        float4 e;
        e.x = b.x - b.z * 0.5f; e.y = b.y - b.w * 0.5f;
        e.z = b.x + b.z * 0.5f; e.w = b.y + b.w * 0.5f;
        int o = bid * PRE + tid;
        g_ts[o] = s;
        g_tb[o] = b;
        g_te[o] = e;
    }
}

// ---------------- kernel 2b: tile-balanced IoU + greedy NMS + emit ----------------
__global__ __launch_bounds__(512) void k_nms2() {
    extern __shared__ char smem[];
    float4*   sxy  = (float4*)smem;
    float4*   sxyw = (float4*)(smem + 8192);
    float*    ssc  = (float*) (smem + 16384);
    float*    sar  = (float*) (smem + 18432);
    uint32_t* mask = (uint32_t*)(smem + 20480);
    uint32_t* scal = (uint32_t*)(smem + 53248);

    int tid = threadIdx.x;
    int bid = blockIdx.x;
    int o = bid * PRE + tid;
    int w = tid >> 5, lane = tid & 31;

    {
        float  s = g_ts[o];
        float4 b = g_tb[o];
        float4 e = g_te[o];
        ssc[tid]  = s;
        sxyw[tid] = b;
        sxy[tid]  = e;
        sar[tid]  = (e.z - e.x) * (e.w - e.y);
    }
    __syncthreads();

    // ---- balanced upper-triangular IoU: 136 32x32 tiles striped over 16 warps ----
    // tile t -> (I,J), I<=J, t = J*(J+1)/2 + I
    for (int t = w; t < 136; t += 16) {
        int J = 0;
        #pragma unroll
        for (int jj = 1; jj < 16; jj++) if ((jj * (jj + 1)) / 2 <= t) J = jj;
        int I = t - (J * (J + 1)) / 2;

        int col = 32 * J + lane;
        float4 me = sxy[col];
        float  aj = sar[col];
        bool diag = (I == J);

        #pragma unroll 4
        for (int r = 0; r < 32; r++) {
            int row = 32 * I + r;
            float4 bi = sxy[row];              // warp-broadcast LDS
            float lx = fmaxf(bi.x, me.x), ly = fmaxf(bi.y, me.y);
            float rx = fminf(bi.z, me.z), ry = fminf(bi.w, me.w);
            float ww = fmaxf(rx - lx, 0.0f), hh = fmaxf(ry - ly, 0.0f);
            float inter = ww * hh;
            float un = fmaxf(sar[row] + aj - inter, 1e-8f);
            bool bit = (inter > 0.5f * un) && (!diag || (lane > r));
            uint32_t bm = __ballot_sync(0xFFFFFFFFu, bit);
            if (lane == 0) mask[row * 16 + J] = bm;
        }
    }
    __syncthreads();

    // ---- chunked single-warp greedy NMS ----
    if (tid < 32) {
        const uint32_t F = 0xFFFFFFFFu;
        int l = tid;
        uint32_t validw = 0;
        if (l < 16) {
            #pragma unroll
            for (int b = 0; b < 32; b++)
                validw |= (ssc[l * 32 + b] > 0.05f) ? (1u << b) : 0u;
        }
        uint32_t keepw = 0xFFFFFFFFu;
        #pragma unroll 1
        for (int g = 0; g < 16; g++) {
            uint32_t vwg  = __shfl_sync(F, validw, g);
            uint32_t kloc = __shfl_sync(F, keepw, g);
            if (l == g) {
                #pragma unroll
                for (int B = 0; B < 4; B++) {
                    uint32_t mm[8];
                    #pragma unroll
                    for (int j = 0; j < 8; j++) mm[j] = mask[(32 * g + 8 * B + j) * 16 + g];
                    #pragma unroll
                    for (int j = 0; j < 8; j++) {
                        int b = 8 * B + j;
                        if (((kloc >> b) & 1u) && ((vwg >> b) & 1u)) kloc &= ~mm[j];
                    }
                }
            }
            uint32_t alive = __shfl_sync(F, kloc & vwg, g);
            if (l == g) keepw = kloc;
            if (l > g && l < 16) {
                uint32_t sup = 0;
                #pragma unroll
                for (int B = 0; B < 4; B++) {
                    uint32_t mm[8];
                    #pragma unroll
                    for (int j = 0; j < 8; j++) mm[j] = mask[(32 * g + 8 * B + j) * 16 + l];
                    #pragma unroll
                    for (int j = 0; j < 8; j++) if ((alive >> (8 * B + j)) & 1u) sup |= mm[j];
                }
                keepw &= ~sup;
            }
        }
        keepw &= validw;
        if (l >= 16) keepw = 0;

        uint32_t pc = __popc(keepw);
        uint32_t incl = pc;
        #pragma unroll
        for (int d = 1; d < 32; d <<= 1) {
            uint32_t n = __shfl_up_sync(F, incl, d);
            if (tid >= d) incl += n;
        }
        uint32_t offs  = incl - pc;
        uint32_t total = __shfl_sync(F, incl, 15);
        if (l < 16) {
            uint32_t slot = offs;
            uint32_t kw = keepw;
            while (kw) {
                int b = __ffs(kw) - 1;
                kw &= kw - 1;
                if (slot < MAXPC) {
                    int gi = bid * MAXPC + (int)slot;
                    int r  = l * 32 + b;
                    g_cls_scores[gi] = ssc[r];
                    g_cls_boxes[gi]  = sxyw[r];
                }
                slot++;
            }
        }
        if (tid == 0) scal[0] = total;
    }
    __syncthreads();
    uint32_t total = scal[0];
    if (tid < MAXPC && (uint32_t)tid >= total) {
        int gi = bid * MAXPC + tid;
        g_cls_scores[gi] = -1.0f;
        g_cls_boxes[gi]  = make_float4(-1.0f, -1.0f, -1.0f, -1.0f);
    }
}

// ---------------- kernel 3: per-image merge + counter reset ----------------
__global__ __launch_bounds__(512) void k_merge(float* __restrict__ out) {
    extern __shared__ char smem[];
    uint32_t* hist = (uint32_t*)smem;
    unsigned long long* keys = (unsigned long long*)smem;
    uint32_t* sufp = (uint32_t*)(smem + 16384);
    uint32_t* wsum = (uint32_t*)(smem + 18440);
    uint32_t* wsuf = (uint32_t*)(smem + 18504);
    uint32_t* scal = (uint32_t*)(smem + 18568);

    int tid = threadIdx.x;
    int img = blockIdx.x;
    const int TOT = N_CLS * MAXPC;

    for (int i = tid; i < 4096; i += 512) hist[i] = 0;
    __syncthreads();
    for (int e0 = 0; e0 < TOT; e0 += 512) {
        int e = e0 + tid;
        uint32_t bin = 0; bool act = (e < TOT);
        if (act) {
            uint32_t b = __float_as_uint(g_cls_scores[img * TOT + e]);
            uint32_t m = (b & 0x80000000u) ? ~b : (b | 0x80000000u);
            bin = m >> 20;
        }
        agg_hist_add(hist, bin, act);
    }
    __syncthreads();

    uint32_t v = 0;
    #pragma unroll
    for (int b = 0; b < 8; b++) v += hist[tid * 8 + ((b + tid) & 7)];
    suffix_scan_512(v, sufp, wsum, wsuf, tid);

    {
        uint32_t cur = sufp[tid], nxt = sufp[tid + 1];
        if (cur >= MAXD && nxt < MAXD) {
            uint32_t run = nxt;
            int T = tid * 8;
            uint32_t above = nxt;
            for (int b = 7; b >= 0; b--) {
                uint32_t h = hist[tid * 8 + b];
                run += h;
                if (run >= MAXD) { T = tid * 8 + b; above = run - h; break; }
            }
            scal[5] = (uint32_t)T;
            scal[1] = above;
        }
        if (tid == 0) { scal[3] = 0; scal[4] = 0; }
    }
    __syncthreads();
    uint32_t T1    = scal[5];
    uint32_t above = scal[1];
    uint32_t need  = MAXD - above;

    for (int i = tid; i < 4096; i += 512) hist[i] = 0;
    __syncthreads();
    for (int e0 = 0; e0 < TOT; e0 += 512) {
        int e = e0 + tid;
        uint32_t bin = 0; bool act = false;
        if (e < TOT) {
            uint32_t b = __float_as_uint(g_cls_scores[img * TOT + e]);
            uint32_t m = (b & 0x80000000u) ? ~b : (b | 0x80000000u);
            if ((m >> 20) == T1) { act = true; bin = (m >> 8) & 0xFFFu; }
        }
        agg_hist_add(hist, bin, act);
    }
    __syncthreads();

    v = 0;
    #pragma unroll
    for (int b = 0; b < 8; b++) v += hist[tid * 8 + ((b + tid) & 7)];
    suffix_scan_512(v, sufp, wsum, wsuf, tid);

    {
        uint32_t cur = sufp[tid], nxt = sufp[tid + 1];
        if (cur >= need && nxt < need) {
            uint32_t run = nxt;
            int T = tid * 8;
            for (int b = 7; b >= 0; b--) {
                run += hist[tid * 8 + b];
                if (run >= need) { T = tid * 8 + b; break; }
            }
            scal[2] = (uint32_t)T;
        }
    }
    __syncthreads();
    uint32_t T2 = scal[2];
    __syncthreads();

    for (int i = tid; i < 1024; i += 512) keys[i] = 0ull;
    __syncthreads();
    for (int e = tid; e < TOT; e += 512) {
        uint32_t b = __float_as_uint(g_cls_scores[img * TOT + e]);
        uint32_t m = (b & 0x80000000u) ? ~b : (b | 0x80000000u);
        uint32_t b1 = m >> 20;
        bool cand = (b1 > T1) || (b1 == T1 && ((m >> 8) & 0xFFFu) >= T2);
        if (cand) {
            uint32_t p = atomicAdd(&scal[3], 1u);
            if (p < 1024)
                keys[p] = ((unsigned long long)m << 32) | (uint32_t)(~(uint32_t)e);
        }
    }
    __syncthreads();
    uint32_t C = min(scal[3], 1024u);
    int SORTN = 1024;
    if      (C <= 128) SORTN = 128;
    else if (C <= 256) SORTN = 256;
    else if (C <= 512) SORTN = 512;

    for (int k = 2; k <= SORTN; k <<= 1) {
        for (int j = k >> 1; j > 0; j >>= 1) {
            for (int i = tid; i < SORTN; i += 512) {
                int l = i ^ j;
                if (l > i) {
                    unsigned long long x = keys[i], y = keys[l];
                    bool up = ((i & k) == 0);
                    if (up ? (x > y) : (x < y)) { keys[i] = y; keys[l] = x; }
                }
            }
            __syncthreads();
        }
    }

    if (tid < MAXD) {
        unsigned long long key = keys[SORTN - 1 - tid];
        uint32_t e = ~((uint32_t)key);
        float s  = g_cls_scores[img * TOT + e];
        float4 b = g_cls_boxes[img * TOT + e];
        bool valid = (s >= 0.05f);
        int cls = (int)(e / MAXPC);
        int o = img * MAXD + tid;
        float4 ob = valid ? b : make_float4(-1.0f, -1.0f, -1.0f, -1.0f);
        ((float4*)out)[o]  = ob;
        out[1600 + o] = valid ? s : -1.0f;
        out[2000 + o] = valid ? (float)cls : -1.0f;
        if (valid) atomicAdd(&scal[4], 1u);
    }
    __syncthreads();
    if (tid == 0) out[2400 + img] = (float)scal[4];

    // reset this image's candidate counters for the next launch
    if (tid < N_CLS) g_cnt[img * N_CLS + tid] = 0;
}

// ---------------- launcher ----------------
extern "C" void kernel_launch(void* const* d_in, const int* in_sizes, int n_in,
                              void* d_out, int out_size) {
    const float* pred = (const float*)d_in[1];
    if (n_in >= 1 && in_sizes[0] == N_IMG * N_ANCH * 84)
        pred = (const float*)d_in[0];

    cudaFuncSetAttribute(k_select, cudaFuncAttributeMaxDynamicSharedMemorySize, SEL_SMEM);
    cudaFuncSetAttribute(k_nms2,   cudaFuncAttributeMaxDynamicSharedMemorySize, NMS2_SMEM);
    cudaFuncSetAttribute(k_merge,  cudaFuncAttributeMaxDynamicSharedMemorySize, MRG_SMEM);

    const int TOTV = N_IMG * N_ANCH * 21;
    k_prep<<<(TOTV + 255) / 256, 256>>>(pred);
    k_select<<<N_IMG * N_CLS, 512, SEL_SMEM>>>(pred);
    k_nms2<<<N_IMG * N_CLS, 512, NMS2_SMEM>>>();
    k_merge<<<N_IMG, 512, MRG_SMEM>>>((float*)d_out);
}

// round 7
// speedup vs baseline: 1.0527x; 1.0527x over previous
#include <cuda_runtime.h>
#include <cstdint>
#include <math.h>

#define N_IMG   4
#define N_ANCH  76725
#define N_CLS   80
#define PRE     512
#define CAND_MAX 2048
#define MAXPC   100
#define MAXD    100

// logit(0.91): s > 0.91 <=> x > 2.3136168
#define XTHR 2.3136168f

#define SEL_SMEM 35072
// k_merge smem: sc[8000]@0 (32000) | hist[4096]@32000 (16384) / keys[1024]@32000 (8192 overlay)
//               sufp@48384 (2052) wsum@50436 wsuf@50500 scal@50564
#define MRG_SMEM 50624

// ---------------- scratch ----------------
__device__ float4 g_boxes[(size_t)N_IMG * N_ANCH];
__device__ unsigned long long g_cand[(size_t)N_IMG * N_CLS * CAND_MAX];
__device__ uint32_t g_cnt[N_IMG * N_CLS];        // zeroed at load; k_merge re-zeros each launch
__device__ float  g_ts[N_IMG * N_CLS * PRE];
__device__ float4 g_tb[N_IMG * N_CLS * PRE];
__device__ float4 g_te[N_IMG * N_CLS * PRE];
__device__ uint32_t g_mask[(size_t)N_IMG * N_CLS * PRE * 16];   // 10.5MB suppression bitmask
__device__ float  g_cls_scores[N_IMG * N_CLS * MAXPC];
__device__ float4 g_cls_boxes [N_IMG * N_CLS * MAXPC];

// ---------------- kernel 1: streaming candidate select + box decode ----------------
__global__ __launch_bounds__(256) void k_prep(const float* __restrict__ pred) {
    const int TOTV = N_IMG * N_ANCH * 21;
    int g = blockIdx.x * 256 + threadIdx.x;
    if (g >= TOTV) return;
    float4 v = ((const float4*)pred)[g];

    int img = g / (N_ANCH * 21);
    int rem = g - img * (N_ANCH * 21);
    int a   = rem / 21;
    int q   = rem - a * 21;

    if (q == 0) {
        int off, fw, stride;
        if      (a < 57600) { off = 0;     fw = 80; stride = 8;   }
        else if (a < 72000) { off = 57600; fw = 40; stride = 16;  }
        else if (a < 75600) { off = 72000; fw = 20; stride = 32;  }
        else if (a < 76500) { off = 75600; fw = 10; stride = 64;  }
        else                { off = 76500; fw = 5;  stride = 128; }
        int rem2 = a - off;
        int cell = rem2 / 9, k = rem2 - cell * 9;
        int iy = cell / fw, ix = cell - iy * fw;
        float sf    = (float)stride;
        float area  = 16.0f * sf * sf;
        float ratio = (k < 3) ? 0.5f : ((k < 6) ? 1.0f : 2.0f);
        int   si    = k % 3;
        float scale = (si == 0) ? 1.0f : ((si == 1) ? 1.2599210498948732f : 1.5874010519681994f);
        float hh = sqrtf(area / ratio);
        float ww = area / hh;
        float cx = (ix + 0.5f) * sf;
        float cy = (iy + 0.5f) * sf;
        float aw = scale * ww, ah = scale * hh;
        float4 b;
        b.x = v.x * 0.1f * aw + cx;
        b.y = v.y * 0.1f * ah + cy;
        b.z = __expf(v.z * 0.2f) * aw;
        b.w = __expf(v.w * 0.2f) * ah;
        g_boxes[(size_t)img * N_ANCH + a] = b;
    } else {
        float xs[4] = {v.x, v.y, v.z, v.w};
        #pragma unroll
        for (int j = 0; j < 4; j++) {
            float x = xs[j];
            if (x > XTHR) {
                int cls = 4 * q + j - 4;
                float s = __fdividef(1.0f, 1.0f + __expf(-x));
                uint32_t mono = __float_as_uint(s) | 0x80000000u;
                int list = img * N_CLS + cls;
                uint32_t idx = atomicAdd(&g_cnt[list], 1u);
                if (idx < CAND_MAX)
                    g_cand[(size_t)list * CAND_MAX + idx] =
                        ((unsigned long long)mono << 32) | (uint32_t)(~(uint32_t)a);
            }
        }
    }
}

__device__ __forceinline__ void suffix_scan_512(uint32_t v, uint32_t* sufp,
                                                uint32_t* wsum, uint32_t* wsuf, int tid) {
    int lane = tid & 31, wid = tid >> 5;
    uint32_t incl = v;
    #pragma unroll
    for (int d = 1; d < 32; d <<= 1) {
        uint32_t n = __shfl_down_sync(0xFFFFFFFFu, incl, d);
        if (lane + d < 32) incl += n;
    }
    if (lane == 0) wsum[wid] = incl;
    __syncthreads();
    if (tid < 16) {
        uint32_t x = wsum[tid];
        #pragma unroll
        for (int d = 1; d < 16; d <<= 1) {
            uint32_t n = __shfl_down_sync(0x0000FFFFu, x, d);
            if (tid + d < 16) x += n;
        }
        wsuf[tid] = x;
    }
    __syncthreads();
    uint32_t below = (wid < 15) ? wsuf[wid + 1] : 0u;
    sufp[tid] = incl + below;
    if (tid == 0) sufp[512] = 0;
    __syncthreads();
}

__device__ __forceinline__ void agg_hist_add(uint32_t* hist, uint32_t bin, bool active) {
    uint32_t amask = __ballot_sync(0xFFFFFFFFu, active);
    if (!active) return;
    uint32_t peers  = __match_any_sync(amask, bin);
    int      leader = __ffs(peers) - 1;
    if ((threadIdx.x & 31) == leader) atomicAdd(&hist[bin], (uint32_t)__popc(peers));
}

// ---------------- kernel 2a: per (img,class) top-512 select + sort ----------------
__global__ __launch_bounds__(512) void k_select(const float* __restrict__ pred) {
    extern __shared__ char smem[];
    uint32_t* hist = (uint32_t*)smem;
    unsigned long long* keys = (unsigned long long*)smem;
    uint32_t* sufp = (uint32_t*)(smem + 32768);
    uint32_t* wsum = (uint32_t*)(smem + 34824);
    uint32_t* wsuf = (uint32_t*)(smem + 34888);
    uint32_t* scal = (uint32_t*)(smem + 34952);

    int tid = threadIdx.x;
    int bid = blockIdx.x;
    int img = bid / N_CLS;
    int cls = bid - img * N_CLS;

    uint32_t cnt = g_cnt[bid];
    int SORTN;

    if (cnt >= PRE && cnt <= CAND_MAX) {
        SORTN = (cnt <= 1024) ? 1024 : CAND_MAX;
        const unsigned long long* src = &g_cand[(size_t)bid * CAND_MAX];
        for (int i = tid; i < SORTN; i += 512)
            keys[i] = (i < (int)cnt) ? src[i] : 0ull;
        __syncthreads();
    } else {
        SORTN = CAND_MAX;
        for (int i = tid; i < 8192; i += 512) hist[i] = 0;
        __syncthreads();
        for (int a = tid; a < N_ANCH; a += 512) {
            float x = pred[((size_t)img * N_ANCH + a) * 84 + 4 + cls];
            float s = __fdividef(1.0f, 1.0f + __expf(-x));
            uint32_t m = __float_as_uint(s) | 0x80000000u;
            agg_hist_add(hist, m >> 19, true);
        }
        __syncthreads();
        uint32_t v = 0;
        #pragma unroll
        for (int b = 0; b < 16; b++) v += hist[tid * 16 + ((b + tid) & 15)];
        suffix_scan_512(v, sufp, wsum, wsuf, tid);
        {
            uint32_t cur = sufp[tid], nxt = sufp[tid + 1];
            if (cur >= PRE && nxt < PRE) {
                uint32_t run = nxt;
                int T = tid * 16;
                for (int b = 15; b >= 0; b--) {
                    run += hist[tid * 16 + b];
                    if (run >= PRE) { T = tid * 16 + b; break; }
                }
                scal[0] = (uint32_t)T << 19;
            }
            if (tid == 0) scal[3] = 0;
        }
        __syncthreads();
        uint32_t thr = scal[0];
        __syncthreads();
        for (int i = tid; i < CAND_MAX; i += 512) keys[i] = 0ull;
        __syncthreads();
        for (int a = tid; a < N_ANCH; a += 512) {
            float x = pred[((size_t)img * N_ANCH + a) * 84 + 4 + cls];
            float s = __fdividef(1.0f, 1.0f + __expf(-x));
            uint32_t m = __float_as_uint(s) | 0x80000000u;
            if (m >= thr) {
                uint32_t p = atomicAdd(&scal[3], 1u);
                if (p < CAND_MAX)
                    keys[p] = ((unsigned long long)m << 32) | (uint32_t)(~(uint32_t)a);
            }
        }
        __syncthreads();
    }

    for (int k = 2; k <= SORTN; k <<= 1) {
        for (int j = k >> 1; j > 0; j >>= 1) {
            for (int i = tid; i < SORTN; i += 512) {
                int l = i ^ j;
                if (l > i) {
                    unsigned long long x = keys[i], y = keys[l];
                    bool up = ((i & k) == 0);
                    if (up ? (x > y) : (x < y)) { keys[i] = y; keys[l] = x; }
                }
            }
            __syncthreads();
        }
    }

    {
        unsigned long long key = keys[SORTN - 1 - tid];
        uint32_t a = ~((uint32_t)key);
        uint32_t m = (uint32_t)(key >> 32);
        float s = __uint_as_float(m ^ 0x80000000u);
        float4 b = g_boxes[(size_t)img * N_ANCH + a];
        float4 e;
        e.x = b.x - b.z * 0.5f; e.y = b.y - b.w * 0.5f;
        e.z = b.x + b.z * 0.5f; e.w = b.y + b.w * 0.5f;
        int o = bid * PRE + tid;
        g_ts[o] = s;
        g_tb[o] = b;
        g_te[o] = e;
    }
}

// ---------------- kernel 2b: IoU bitmask, fine-grained (4 blocks per task) ----------------
__global__ __launch_bounds__(256) void k_iou() {
    __shared__ float4 sxy[PRE];
    __shared__ float  sar[PRE];

    int tid  = threadIdx.x;
    int task = blockIdx.x >> 2;
    int sub  = blockIdx.x & 3;
    int w = tid >> 5, lane = tid & 31;

    for (int i = tid; i < PRE; i += 256) {
        float4 e = g_te[task * PRE + i];
        sxy[i] = e;
        sar[i] = (e.z - e.x) * (e.w - e.y);
    }
    __syncthreads();

    uint32_t* gm = &g_mask[(size_t)task * PRE * 16];
    int tbase = sub * 34;

    // tiles [tbase, tbase+34), striped over 8 warps
    for (int t = tbase + w; t < tbase + 34; t += 8) {
        int J = 0;
        #pragma unroll
        for (int jj = 1; jj < 16; jj++) if ((jj * (jj + 1)) / 2 <= t) J = jj;
        int I = t - (J * (J + 1)) / 2;

        int col = 32 * J + lane;
        float4 me = sxy[col];
        float  aj = sar[col];
        bool diag = (I == J);

        #pragma unroll 4
        for (int r = 0; r < 32; r++) {
            int row = 32 * I + r;
            float4 bi = sxy[row];
            float lx = fmaxf(bi.x, me.x), ly = fmaxf(bi.y, me.y);
            float rx = fminf(bi.z, me.z), ry = fminf(bi.w, me.w);
            float ww = fmaxf(rx - lx, 0.0f), hh = fmaxf(ry - ly, 0.0f);
            float inter = ww * hh;
            float un = fmaxf(sar[row] + aj - inter, 1e-8f);
            bool bit = (inter > 0.5f * un) && (!diag || (lane > r));
            uint32_t bm = __ballot_sync(0xFFFFFFFFu, bit);
            if (lane == 0) gm[row * 16 + J] = bm;
        }
    }
}

// ---------------- kernel 2c: greedy NMS + per-class emit ----------------
__global__ __launch_bounds__(512) void k_greedy() {
    __shared__ uint32_t mask[PRE * 16];    // 32KB
    __shared__ float    ssc[PRE];          // 2KB
    __shared__ float4   sxyw[PRE];         // 8KB
    __shared__ uint32_t scal[4];

    int tid = threadIdx.x;
    int bid = blockIdx.x;

    // bulk-load mask (vectorized, coalesced)
    {
        const uint4* src = (const uint4*)&g_mask[(size_t)bid * PRE * 16];
        uint4* dst = (uint4*)mask;
        for (int i = tid; i < PRE * 4; i += 512) dst[i] = src[i];
    }
    ssc[tid]  = g_ts[bid * PRE + tid];
    sxyw[tid] = g_tb[bid * PRE + tid];
    __syncthreads();

    if (tid < 32) {
        const uint32_t F = 0xFFFFFFFFu;
        int l = tid;
        uint32_t validw = 0;
        if (l < 16) {
            #pragma unroll
            for (int b = 0; b < 32; b++)
                validw |= (ssc[l * 32 + b] > 0.05f) ? (1u << b) : 0u;
        }
        uint32_t keepw = 0xFFFFFFFFu;
        #pragma unroll 1
        for (int g = 0; g < 16; g++) {
            uint32_t vwg  = __shfl_sync(F, validw, g);
            uint32_t kloc = __shfl_sync(F, keepw, g);
            if (l == g) {
                #pragma unroll
                for (int B = 0; B < 4; B++) {
                    uint32_t mm[8];
                    #pragma unroll
                    for (int j = 0; j < 8; j++) mm[j] = mask[(32 * g + 8 * B + j) * 16 + g];
                    #pragma unroll
                    for (int j = 0; j < 8; j++) {
                        int b = 8 * B + j;
                        if (((kloc >> b) & 1u) && ((vwg >> b) & 1u)) kloc &= ~mm[j];
                    }
                }
            }
            uint32_t alive = __shfl_sync(F, kloc & vwg, g);
            if (l == g) keepw = kloc;
            if (l > g && l < 16) {
                uint32_t sup = 0;
                #pragma unroll
                for (int B = 0; B < 4; B++) {
                    uint32_t mm[8];
                    #pragma unroll
                    for (int j = 0; j < 8; j++) mm[j] = mask[(32 * g + 8 * B + j) * 16 + l];
                    #pragma unroll
                    for (int j = 0; j < 8; j++) if ((alive >> (8 * B + j)) & 1u) sup |= mm[j];
                }
                keepw &= ~sup;
            }
        }
        keepw &= validw;
        if (l >= 16) keepw = 0;

        uint32_t pc = __popc(keepw);
        uint32_t incl = pc;
        #pragma unroll
        for (int d = 1; d < 32; d <<= 1) {
            uint32_t n = __shfl_up_sync(F, incl, d);
            if (tid >= d) incl += n;
        }
        uint32_t offs  = incl - pc;
        uint32_t total = __shfl_sync(F, incl, 15);
        if (l < 16) {
            uint32_t slot = offs;
            uint32_t kw = keepw;
            while (kw) {
                int b = __ffs(kw) - 1;
                kw &= kw - 1;
                if (slot < MAXPC) {
                    int gi = bid * MAXPC + (int)slot;
                    int r  = l * 32 + b;
                    g_cls_scores[gi] = ssc[r];
                    g_cls_boxes[gi]  = sxyw[r];
                }
                slot++;
            }
        }
        if (tid == 0) scal[0] = total;
    }
    __syncthreads();
    uint32_t total = scal[0];
    if (tid < MAXPC && (uint32_t)tid >= total) {
        int gi = bid * MAXPC + tid;
        g_cls_scores[gi] = -1.0f;
        g_cls_boxes[gi]  = make_float4(-1.0f, -1.0f, -1.0f, -1.0f);
    }
}

// ---------------- kernel 3: per-image merge (smem-staged) + counter reset ----------------
__global__ __launch_bounds__(512) void k_merge(float* __restrict__ out) {
    extern __shared__ char smem[];
    float*    sc   = (float*)smem;                          // 8000 floats
    uint32_t* hist = (uint32_t*)(smem + 32000);             // 4096 bins
    unsigned long long* keys = (unsigned long long*)(smem + 32000);  // overlay
    uint32_t* sufp = (uint32_t*)(smem + 48384);
    uint32_t* wsum = (uint32_t*)(smem + 50436);
    uint32_t* wsuf = (uint32_t*)(smem + 50500);
    uint32_t* scal = (uint32_t*)(smem + 50564);

    int tid = threadIdx.x;
    int img = blockIdx.x;
    const int TOT = N_CLS * MAXPC;   // 8000

    // stage all scores in smem (one coalesced sweep, high MLP)
    for (int e = tid; e < TOT; e += 512) sc[e] = g_cls_scores[img * TOT + e];
    for (int i = tid; i < 4096; i += 512) hist[i] = 0;
    __syncthreads();

    // pass 1: coarse on bits [31:20]
    for (int e0 = 0; e0 < TOT; e0 += 512) {
        int e = e0 + tid;
        uint32_t bin = 0; bool act = (e < TOT);
        if (act) {
            uint32_t b = __float_as_uint(sc[e]);
            uint32_t m = (b & 0x80000000u) ? ~b : (b | 0x80000000u);
            bin = m >> 20;
        }
        agg_hist_add(hist, bin, act);
    }
    __syncthreads();

    uint32_t v = 0;
    #pragma unroll
    for (int b = 0; b < 8; b++) v += hist[tid * 8 + ((b + tid) & 7)];
    suffix_scan_512(v, sufp, wsum, wsuf, tid);

    {
        uint32_t cur = sufp[tid], nxt = sufp[tid + 1];
        if (cur >= MAXD && nxt < MAXD) {
            uint32_t run = nxt;
            int T = tid * 8;
            uint32_t above = nxt;
            for (int b = 7; b >= 0; b--) {
                uint32_t h = hist[tid * 8 + b];
                run += h;
                if (run >= MAXD) { T = tid * 8 + b; above = run - h; break; }
            }
            scal[5 & 3] = 0;  // placeholder no-op
            sufp[512] = 0;
            scal[1] = above;
            scal[0] = (uint32_t)T;
        }
        if (tid == 0) { scal[3] = 0; }
    }
    __syncthreads();
    uint32_t T1    = scal[0];
    uint32_t above = scal[1];
    uint32_t need  = MAXD - above;

    // pass 2: refine within bin T1 on bits [19:8]
    for (int i = tid; i < 4096; i += 512) hist[i] = 0;
    __syncthreads();
    for (int e0 = 0; e0 < TOT; e0 += 512) {
        int e = e0 + tid;
        uint32_t bin = 0; bool act = false;
        if (e < TOT) {
            uint32_t b = __float_as_uint(sc[e]);
            uint32_t m = (b & 0x80000000u) ? ~b : (b | 0x80000000u);
            if ((m >> 20) == T1) { act = true; bin = (m >> 8) & 0xFFFu; }
        }
        agg_hist_add(hist, bin, act);
    }
    __syncthreads();

    v = 0;
    #pragma unroll
    for (int b = 0; b < 8; b++) v += hist[tid * 8 + ((b + tid) & 7)];
    suffix_scan_512(v, sufp, wsum, wsuf, tid);

    {
        uint32_t cur = sufp[tid], nxt = sufp[tid + 1];
        if (cur >= need && nxt < need) {
            uint32_t run = nxt;
            int T = tid * 8;
            for (int b = 7; b >= 0; b--) {
                run += hist[tid * 8 + b];
                if (run >= need) { T = tid * 8 + b; break; }
            }
            scal[2] = (uint32_t)T;
        }
    }
    __syncthreads();
    uint32_t T2 = scal[2];
    __syncthreads();

    // compaction (keys overlays hist)
    for (int i = tid; i < 1024; i += 512) keys[i] = 0ull;
    __syncthreads();
    for (int e = tid; e < TOT; e += 512) {
        uint32_t b = __float_as_uint(sc[e]);
        uint32_t m = (b & 0x80000000u) ? ~b : (b | 0x80000000u);
        uint32_t b1 = m >> 20;
        bool cand = (b1 > T1) || (b1 == T1 && ((m >> 8) & 0xFFFu) >= T2);
        if (cand) {
            uint32_t p = atomicAdd(&scal[3], 1u);
            if (p < 1024)
                keys[p] = ((unsigned long long)m << 32) | (uint32_t)(~(uint32_t)e);
        }
    }
    __syncthreads();
    uint32_t C = min(scal[3], 1024u);
    int SORTN = 1024;
    if      (C <= 128) SORTN = 128;
    else if (C <= 256) SORTN = 256;
    else if (C <= 512) SORTN = 512;

    for (int k = 2; k <= SORTN; k <<= 1) {
        for (int j = k >> 1; j > 0; j >>= 1) {
            for (int i = tid; i < SORTN; i += 512) {
                int l = i ^ j;
                if (l > i) {
                    unsigned long long x = keys[i], y = keys[l];
                    bool up = ((i & k) == 0);
                    if (up ? (x > y) : (x < y)) { keys[i] = y; keys[l] = x; }
                }
            }
            __syncthreads();
        }
    }

    if (tid == 0) scal[1] = 0;
    __syncthreads();
    if (tid < MAXD) {
        unsigned long long key = keys[SORTN - 1 - tid];
        uint32_t e = ~((uint32_t)key);
        float s  = sc[e];
        float4 b = g_cls_boxes[img * TOT + e];
        bool valid = (s >= 0.05f);
        int cls = (int)(e / MAXPC);
        int o = img * MAXD + tid;
        float4 ob = valid ? b : make_float4(-1.0f, -1.0f, -1.0f, -1.0f);
        ((float4*)out)[o]  = ob;
        out[1600 + o] = valid ? s : -1.0f;
        out[2000 + o] = valid ? (float)cls : -1.0f;
        if (valid) atomicAdd(&scal[1], 1u);
    }
    __syncthreads();
    if (tid == 0) out[2400 + img] = (float)scal[1];

    // reset this image's candidate counters for the next launch
    if (tid < N_CLS) g_cnt[img * N_CLS + tid] = 0;
}

// ---------------- launcher ----------------
extern "C" void kernel_launch(void* const* d_in, const int* in_sizes, int n_in,
                              void* d_out, int out_size) {
    const float* pred = (const float*)d_in[1];
    if (n_in >= 1 && in_sizes[0] == N_IMG * N_ANCH * 84)
        pred = (const float*)d_in[0];

    cudaFuncSetAttribute(k_select, cudaFuncAttributeMaxDynamicSharedMemorySize, SEL_SMEM);
    cudaFuncSetAttribute(k_merge,  cudaFuncAttributeMaxDynamicSharedMemorySize, MRG_SMEM);

    const int TOTV = N_IMG * N_ANCH * 21;
    k_prep<<<(TOTV + 255) / 256, 256>>>(pred);
    k_select<<<N_IMG * N_CLS, 512, SEL_SMEM>>>(pred);
    k_iou<<<N_IMG * N_CLS * 4, 256>>>();
    k_greedy<<<N_IMG * N_CLS, 512>>>();
    k_merge<<<N_IMG, 512, MRG_SMEM>>>((float*)d_out);
}

// round 8
// speedup vs baseline: 1.2521x; 1.1894x over previous
#include <cuda_runtime.h>
#include <cstdint>
#include <math.h>

#define N_IMG   4
#define N_ANCH  76725
#define N_CLS   80
#define PRE     512
#define FASTK   256
#define CAND_MAX 2048
#define MAXPC   100
#define MAXD    100

// logit(0.91): s > 0.91 <=> x > 2.3136168
#define XTHR 2.3136168f

#define SEL_SMEM 35072
// k_nms smem: sxy@0 8K, sxyw@8192 8K, ssc@16384 2K, sar@18432 2K, mask@20480 32K, scal@53248
#define NMS_SMEM 53312
// k_merge smem: sc[8000]@0 | hist[4096]@32000 / keys[1024]@32000, sufp@48384, wsum@50436, wsuf@50500, scal@50564
#define MRG_SMEM 50624

// ---------------- scratch ----------------
__device__ float4 g_boxes[(size_t)N_IMG * N_ANCH];
__device__ unsigned long long g_cand[(size_t)N_IMG * N_CLS * CAND_MAX];
__device__ uint32_t g_cnt[N_IMG * N_CLS];        // zeroed at load; k_merge re-zeros each launch
__device__ float  g_ts[N_IMG * N_CLS * PRE];
__device__ float4 g_tb[N_IMG * N_CLS * PRE];
__device__ float4 g_te[N_IMG * N_CLS * PRE];
__device__ float  g_cls_scores[N_IMG * N_CLS * MAXPC];
__device__ float4 g_cls_boxes [N_IMG * N_CLS * MAXPC];

// ---------------- kernel 1: streaming candidate select + box decode ----------------
__global__ __launch_bounds__(256) void k_prep(const float* __restrict__ pred) {
    const int TOTV = N_IMG * N_ANCH * 21;
    int g = blockIdx.x * 256 + threadIdx.x;
    if (g >= TOTV) return;
    float4 v = ((const float4*)pred)[g];

    int img = g / (N_ANCH * 21);
    int rem = g - img * (N_ANCH * 21);
    int a   = rem / 21;
    int q   = rem - a * 21;

    if (q == 0) {
        int off, fw, stride;
        if      (a < 57600) { off = 0;     fw = 80; stride = 8;   }
        else if (a < 72000) { off = 57600; fw = 40; stride = 16;  }
        else if (a < 75600) { off = 72000; fw = 20; stride = 32;  }
        else if (a < 76500) { off = 75600; fw = 10; stride = 64;  }
        else                { off = 76500; fw = 5;  stride = 128; }
        int rem2 = a - off;
        int cell = rem2 / 9, k = rem2 - cell * 9;
        int iy = cell / fw, ix = cell - iy * fw;
        float sf    = (float)stride;
        float area  = 16.0f * sf * sf;
        float ratio = (k < 3) ? 0.5f : ((k < 6) ? 1.0f : 2.0f);
        int   si    = k % 3;
        float scale = (si == 0) ? 1.0f : ((si == 1) ? 1.2599210498948732f : 1.5874010519681994f);
        float hh = sqrtf(area / ratio);
        float ww = area / hh;
        float cx = (ix + 0.5f) * sf;
        float cy = (iy + 0.5f) * sf;
        float aw = scale * ww, ah = scale * hh;
        float4 b;
        b.x = v.x * 0.1f * aw + cx;
        b.y = v.y * 0.1f * ah + cy;
        b.z = __expf(v.z * 0.2f) * aw;
        b.w = __expf(v.w * 0.2f) * ah;
        g_boxes[(size_t)img * N_ANCH + a] = b;
    } else {
        float xs[4] = {v.x, v.y, v.z, v.w};
        #pragma unroll
        for (int j = 0; j < 4; j++) {
            float x = xs[j];
            if (x > XTHR) {
                int cls = 4 * q + j - 4;
                float s = __fdividef(1.0f, 1.0f + __expf(-x));
                uint32_t mono = __float_as_uint(s) | 0x80000000u;
                int list = img * N_CLS + cls;
                uint32_t idx = atomicAdd(&g_cnt[list], 1u);
                if (idx < CAND_MAX)
                    g_cand[(size_t)list * CAND_MAX + idx] =
                        ((unsigned long long)mono << 32) | (uint32_t)(~(uint32_t)a);
            }
        }
    }
}

__device__ __forceinline__ void suffix_scan_512(uint32_t v, uint32_t* sufp,
                                                uint32_t* wsum, uint32_t* wsuf, int tid) {
    int lane = tid & 31, wid = tid >> 5;
    uint32_t incl = v;
    #pragma unroll
    for (int d = 1; d < 32; d <<= 1) {
        uint32_t n = __shfl_down_sync(0xFFFFFFFFu, incl, d);
        if (lane + d < 32) incl += n;
    }
    if (lane == 0) wsum[wid] = incl;
    __syncthreads();
    if (tid < 16) {
        uint32_t x = wsum[tid];
        #pragma unroll
        for (int d = 1; d < 16; d <<= 1) {
            uint32_t n = __shfl_down_sync(0x0000FFFFu, x, d);
            if (tid + d < 16) x += n;
        }
        wsuf[tid] = x;
    }
    __syncthreads();
    uint32_t below = (wid < 15) ? wsuf[wid + 1] : 0u;
    sufp[tid] = incl + below;
    if (tid == 0) sufp[512] = 0;
    __syncthreads();
}

__device__ __forceinline__ void agg_hist_add(uint32_t* hist, uint32_t bin, bool active) {
    uint32_t amask = __ballot_sync(0xFFFFFFFFu, active);
    if (!active) return;
    uint32_t peers  = __match_any_sync(amask, bin);
    int      leader = __ffs(peers) - 1;
    if ((threadIdx.x & 31) == leader) atomicAdd(&hist[bin], (uint32_t)__popc(peers));
}

// ---------------- kernel 2a: per (img,class) top-512 select + sort ----------------
__global__ __launch_bounds__(512) void k_select(const float* __restrict__ pred) {
    extern __shared__ char smem[];
    uint32_t* hist = (uint32_t*)smem;
    unsigned long long* keys = (unsigned long long*)smem;
    uint32_t* sufp = (uint32_t*)(smem + 32768);
    uint32_t* wsum = (uint32_t*)(smem + 34824);
    uint32_t* wsuf = (uint32_t*)(smem + 34888);
    uint32_t* scal = (uint32_t*)(smem + 34952);

    int tid = threadIdx.x;
    int bid = blockIdx.x;
    int img = bid / N_CLS;
    int cls = bid - img * N_CLS;

    uint32_t cnt = g_cnt[bid];
    int SORTN;

    if (cnt >= PRE && cnt <= CAND_MAX) {
        SORTN = (cnt <= 1024) ? 1024 : CAND_MAX;
        const unsigned long long* src = &g_cand[(size_t)bid * CAND_MAX];
        for (int i = tid; i < SORTN; i += 512)
            keys[i] = (i < (int)cnt) ? src[i] : 0ull;
        __syncthreads();
    } else {
        SORTN = CAND_MAX;
        for (int i = tid; i < 8192; i += 512) hist[i] = 0;
        __syncthreads();
        for (int a = tid; a < N_ANCH; a += 512) {
            float x = pred[((size_t)img * N_ANCH + a) * 84 + 4 + cls];
            float s = __fdividef(1.0f, 1.0f + __expf(-x));
            uint32_t m = __float_as_uint(s) | 0x80000000u;
            agg_hist_add(hist, m >> 19, true);
        }
        __syncthreads();
        uint32_t v = 0;
        #pragma unroll
        for (int b = 0; b < 16; b++) v += hist[tid * 16 + ((b + tid) & 15)];
        suffix_scan_512(v, sufp, wsum, wsuf, tid);
        {
            uint32_t cur = sufp[tid], nxt = sufp[tid + 1];
            if (cur >= PRE && nxt < PRE) {
                uint32_t run = nxt;
                int T = tid * 16;
                for (int b = 15; b >= 0; b--) {
                    run += hist[tid * 16 + b];
                    if (run >= PRE) { T = tid * 16 + b; break; }
                }
                scal[0] = (uint32_t)T << 19;
            }
            if (tid == 0) scal[3] = 0;
        }
        __syncthreads();
        uint32_t thr = scal[0];
        __syncthreads();
        for (int i = tid; i < CAND_MAX; i += 512) keys[i] = 0ull;
        __syncthreads();
        for (int a = tid; a < N_ANCH; a += 512) {
            float x = pred[((size_t)img * N_ANCH + a) * 84 + 4 + cls];
            float s = __fdividef(1.0f, 1.0f + __expf(-x));
            uint32_t m = __float_as_uint(s) | 0x80000000u;
            if (m >= thr) {
                uint32_t p = atomicAdd(&scal[3], 1u);
                if (p < CAND_MAX)
                    keys[p] = ((unsigned long long)m << 32) | (uint32_t)(~(uint32_t)a);
            }
        }
        __syncthreads();
    }

    for (int k = 2; k <= SORTN; k <<= 1) {
        for (int j = k >> 1; j > 0; j >>= 1) {
            for (int i = tid; i < SORTN; i += 512) {
                int l = i ^ j;
                if (l > i) {
                    unsigned long long x = keys[i], y = keys[l];
                    bool up = ((i & k) == 0);
                    if (up ? (x > y) : (x < y)) { keys[i] = y; keys[l] = x; }
                }
            }
            __syncthreads();
        }
    }

    {
        unsigned long long key = keys[SORTN - 1 - tid];
        uint32_t a = ~((uint32_t)key);
        uint32_t m = (uint32_t)(key >> 32);
        float s = __uint_as_float(m ^ 0x80000000u);
        float4 b = g_boxes[(size_t)img * N_ANCH + a];
        float4 e;
        e.x = b.x - b.z * 0.5f; e.y = b.y - b.w * 0.5f;
        e.z = b.x + b.z * 0.5f; e.w = b.y + b.w * 0.5f;
        int o = bid * PRE + tid;
        g_ts[o] = s;
        g_tb[o] = b;
        g_te[o] = e;
    }
}

// compute IoU bitmask tiles [t0,t1) striped over 16 warps; mask[row*16+J]
__device__ __forceinline__ void iou_tiles(const float4* sxy, const float* sar,
                                          uint32_t* mask, int t0, int t1,
                                          int w, int lane) {
    for (int t = t0 + w; t < t1; t += 16) {
        int J = 0;
        #pragma unroll
        for (int jj = 1; jj < 16; jj++) if ((jj * (jj + 1)) / 2 <= t) J = jj;
        int I = t - (J * (J + 1)) / 2;

        int col = 32 * J + lane;
        float4 me = sxy[col];
        float  aj = sar[col];
        bool diag = (I == J);

        #pragma unroll 4
        for (int r = 0; r < 32; r++) {
            int row = 32 * I + r;
            float4 bi = sxy[row];
            float lx = fmaxf(bi.x, me.x), ly = fmaxf(bi.y, me.y);
            float rx = fminf(bi.z, me.z), ry = fminf(bi.w, me.w);
            float ww = fmaxf(rx - lx, 0.0f), hh = fmaxf(ry - ly, 0.0f);
            float inter = ww * hh;
            float un = fmaxf(sar[row] + aj - inter, 1e-8f);
            bool bit = (inter > 0.5f * un) && (!diag || (lane > r));
            uint32_t bm = __ballot_sync(0xFFFFFFFFu, bit);
            if (lane == 0) mask[row * 16 + J] = bm;
        }
    }
}

// greedy over G groups (G*32 boxes); emits keepers; returns via scal[0]
__device__ __forceinline__ void greedy_emit(const float* ssc, const float4* sxyw,
                                            const uint32_t* mask, uint32_t* scal,
                                            int G, int bid, int tid) {
    if (tid < 32) {
        const uint32_t F = 0xFFFFFFFFu;
        int l = tid;
        uint32_t validw = 0;
        if (l < G) {
            #pragma unroll
            for (int b = 0; b < 32; b++)
                validw |= (ssc[l * 32 + b] > 0.05f) ? (1u << b) : 0u;
        }
        uint32_t keepw = 0xFFFFFFFFu;
        #pragma unroll 1
        for (int g = 0; g < G; g++) {
            uint32_t vwg  = __shfl_sync(F, validw, g);
            uint32_t kloc = __shfl_sync(F, keepw, g);
            if (l == g) {
                #pragma unroll
                for (int B = 0; B < 4; B++) {
                    uint32_t mm[8];
                    #pragma unroll
                    for (int j = 0; j < 8; j++) mm[j] = mask[(32 * g + 8 * B + j) * 16 + g];
                    #pragma unroll
                    for (int j = 0; j < 8; j++) {
                        int b = 8 * B + j;
                        if (((kloc >> b) & 1u) && ((vwg >> b) & 1u)) kloc &= ~mm[j];
                    }
                }
            }
            uint32_t alive = __shfl_sync(F, kloc & vwg, g);
            if (l == g) keepw = kloc;
            if (l > g && l < G) {
                uint32_t sup = 0;
                #pragma unroll
                for (int B = 0; B < 4; B++) {
                    uint32_t mm[8];
                    #pragma unroll
                    for (int j = 0; j < 8; j++) mm[j] = mask[(32 * g + 8 * B + j) * 16 + l];
                    #pragma unroll
                    for (int j = 0; j < 8; j++) if ((alive >> (8 * B + j)) & 1u) sup |= mm[j];
                }
                keepw &= ~sup;
            }
        }
        keepw &= validw;
        if (l >= G) keepw = 0;

        uint32_t pc = __popc(keepw);
        uint32_t incl = pc;
        #pragma unroll
        for (int d = 1; d < 32; d <<= 1) {
            uint32_t n = __shfl_up_sync(F, incl, d);
            if (tid >= d) incl += n;
        }
        uint32_t offs  = incl - pc;
        uint32_t total = __shfl_sync(F, incl, G - 1);
        if (l < G) {
            uint32_t slot = offs;
            uint32_t kw = keepw;
            while (kw) {
                int b = __ffs(kw) - 1;
                kw &= kw - 1;
                if (slot < MAXPC) {
                    int gi = bid * MAXPC + (int)slot;
                    int r  = l * 32 + b;
                    g_cls_scores[gi] = ssc[r];
                    g_cls_boxes[gi]  = sxyw[r];
                }
                slot++;
            }
        }
        if (tid == 0) scal[0] = total;
    }
}

// ---------------- kernel 2b: fused NMS, 256-prefix fast path + 512 fallback ----------------
__global__ __launch_bounds__(512) void k_nms() {
    extern __shared__ char smem[];
    float4*   sxy  = (float4*)smem;
    float4*   sxyw = (float4*)(smem + 8192);
    float*    ssc  = (float*) (smem + 16384);
    float*    sar  = (float*) (smem + 18432);
    uint32_t* mask = (uint32_t*)(smem + 20480);
    uint32_t* scal = (uint32_t*)(smem + 53248);

    int tid = threadIdx.x;
    int bid = blockIdx.x;
    int o = bid * PRE + tid;
    int w = tid >> 5, lane = tid & 31;

    {
        float  s = g_ts[o];
        float4 b = g_tb[o];
        float4 e = g_te[o];
        ssc[tid]  = s;
        sxyw[tid] = b;
        sxy[tid]  = e;
        sar[tid]  = (e.z - e.x) * (e.w - e.y);
    }
    __syncthreads();

    // fast path: 36 tiles covering the top-256 upper triangle
    iou_tiles(sxy, sar, mask, 0, 36, w, lane);
    __syncthreads();
    greedy_emit(ssc, sxyw, mask, scal, 8, bid, tid);
    __syncthreads();

    uint32_t total = scal[0];
    if (total >= MAXD) return;   // exact: top-100 keepers all within top-256

    // fallback (~never): extend mask to full 512, redo greedy over 16 groups
    iou_tiles(sxy, sar, mask, 36, 136, w, lane);
    __syncthreads();
    greedy_emit(ssc, sxyw, mask, scal, 16, bid, tid);
    __syncthreads();
    total = scal[0];
    if (tid < MAXPC && (uint32_t)tid >= total) {
        int gi = bid * MAXPC + tid;
        g_cls_scores[gi] = -1.0f;
        g_cls_boxes[gi]  = make_float4(-1.0f, -1.0f, -1.0f, -1.0f);
    }
}

// ---------------- kernel 3: per-image merge (smem-staged) + counter reset ----------------
__global__ __launch_bounds__(512) void k_merge(float* __restrict__ out) {
    extern __shared__ char smem[];
    float*    sc   = (float*)smem;                          // 8000 floats
    uint32_t* hist = (uint32_t*)(smem + 32000);             // 4096 bins
    unsigned long long* keys = (unsigned long long*)(smem + 32000);  // overlay
    uint32_t* sufp = (uint32_t*)(smem + 48384);
    uint32_t* wsum = (uint32_t*)(smem + 50436);
    uint32_t* wsuf = (uint32_t*)(smem + 50500);
    uint32_t* scal = (uint32_t*)(smem + 50564);

    int tid = threadIdx.x;
    int img = blockIdx.x;
    const int TOT = N_CLS * MAXPC;   // 8000

    for (int e = tid; e < TOT; e += 512) sc[e] = g_cls_scores[img * TOT + e];
    for (int i = tid; i < 4096; i += 512) hist[i] = 0;
    __syncthreads();

    // pass 1: coarse on bits [31:20]
    for (int e0 = 0; e0 < TOT; e0 += 512) {
        int e = e0 + tid;
        uint32_t bin = 0; bool act = (e < TOT);
        if (act) {
            uint32_t b = __float_as_uint(sc[e]);
            uint32_t m = (b & 0x80000000u) ? ~b : (b | 0x80000000u);
            bin = m >> 20;
        }
        agg_hist_add(hist, bin, act);
    }
    __syncthreads();

    uint32_t v = 0;
    #pragma unroll
    for (int b = 0; b < 8; b++) v += hist[tid * 8 + ((b + tid) & 7)];
    suffix_scan_512(v, sufp, wsum, wsuf, tid);

    {
        uint32_t cur = sufp[tid], nxt = sufp[tid + 1];
        if (cur >= MAXD && nxt < MAXD) {
            uint32_t run = nxt;
            int T = tid * 8;
            uint32_t above = nxt;
            for (int b = 7; b >= 0; b--) {
                uint32_t h = hist[tid * 8 + b];
                run += h;
                if (run >= MAXD) { T = tid * 8 + b; above = run - h; break; }
            }
            scal[0] = (uint32_t)T;
            scal[1] = above;
        }
        if (tid == 0) scal[3] = 0;
    }
    __syncthreads();
    uint32_t T1    = scal[0];
    uint32_t above = scal[1];
    uint32_t need  = MAXD - above;

    // pass 2: refine within bin T1 on bits [19:8]
    for (int i = tid; i < 4096; i += 512) hist[i] = 0;
    __syncthreads();
    for (int e0 = 0; e0 < TOT; e0 += 512) {
        int e = e0 + tid;
        uint32_t bin = 0; bool act = false;
        if (e < TOT) {
            uint32_t b = __float_as_uint(sc[e]);
            uint32_t m = (b & 0x80000000u) ? ~b : (b | 0x80000000u);
            if ((m >> 20) == T1) { act = true; bin = (m >> 8) & 0xFFFu; }
        }
        agg_hist_add(hist, bin, act);
    }
    __syncthreads();

    v = 0;
    #pragma unroll
    for (int b = 0; b < 8; b++) v += hist[tid * 8 + ((b + tid) & 7)];
    suffix_scan_512(v, sufp, wsum, wsuf, tid);

    {
        uint32_t cur = sufp[tid], nxt = sufp[tid + 1];
        if (cur >= need && nxt < need) {
            uint32_t run = nxt;
            int T = tid * 8;
            for (int b = 7; b >= 0; b--) {
                run += hist[tid * 8 + b];
                if (run >= need) { T = tid * 8 + b; break; }
            }
            scal[2] = (uint32_t)T;
        }
    }
    __syncthreads();
    uint32_t T2 = scal[2];
    __syncthreads();

    // compaction (keys overlays hist)
    for (int i = tid; i < 1024; i += 512) keys[i] = 0ull;
    __syncthreads();
    for (int e = tid; e < TOT; e += 512) {
        uint32_t b = __float_as_uint(sc[e]);
        uint32_t m = (b & 0x80000000u) ? ~b : (b | 0x80000000u);
        uint32_t b1 = m >> 20;
        bool cand = (b1 > T1) || (b1 == T1 && ((m >> 8) & 0xFFFu) >= T2);
        if (cand) {
            uint32_t p = atomicAdd(&scal[3], 1u);
            if (p < 1024)
                keys[p] = ((unsigned long long)m << 32) | (uint32_t)(~(uint32_t)e);
        }
    }
    __syncthreads();
    uint32_t C = min(scal[3], 1024u);
    int SORTN = 1024;
    if      (C <= 128) SORTN = 128;
    else if (C <= 256) SORTN = 256;
    else if (C <= 512) SORTN = 512;

    for (int k = 2; k <= SORTN; k <<= 1) {
        for (int j = k >> 1; j > 0; j >>= 1) {
            for (int i = tid; i < SORTN; i += 512) {
                int l = i ^ j;
                if (l > i) {
                    unsigned long long x = keys[i], y = keys[l];
                    bool up = ((i & k) == 0);
                    if (up ? (x > y) : (x < y)) { keys[i] = y; keys[l] = x; }
                }
            }
            __syncthreads();
        }
    }

    if (tid == 0) scal[1] = 0;
    __syncthreads();
    if (tid < MAXD) {
        unsigned long long key = keys[SORTN - 1 - tid];
        uint32_t e = ~((uint32_t)key);
        float s  = sc[e];
        float4 b = g_cls_boxes[img * TOT + e];
        bool valid = (s >= 0.05f);
        int cls = (int)(e / MAXPC);
        int o = img * MAXD + tid;
        float4 ob = valid ? b : make_float4(-1.0f, -1.0f, -1.0f, -1.0f);
        ((float4*)out)[o]  = ob;
        out[1600 + o] = valid ? s : -1.0f;
        out[2000 + o] = valid ? (float)cls : -1.0f;
        if (valid) atomicAdd(&scal[1], 1u);
    }
    __syncthreads();
    if (tid == 0) out[2400 + img] = (float)scal[1];

    // reset this image's candidate counters for the next launch
    if (tid < N_CLS) g_cnt[img * N_CLS + tid] = 0;
}

// ---------------- launcher ----------------
extern "C" void kernel_launch(void* const* d_in, const int* in_sizes, int n_in,
                              void* d_out, int out_size) {
    const float* pred = (const float*)d_in[1];
    if (n_in >= 1 && in_sizes[0] == N_IMG * N_ANCH * 84)
        pred = (const float*)d_in[0];

    cudaFuncSetAttribute(k_select, cudaFuncAttributeMaxDynamicSharedMemorySize, SEL_SMEM);
    cudaFuncSetAttribute(k_nms,    cudaFuncAttributeMaxDynamicSharedMemorySize, NMS_SMEM);
    cudaFuncSetAttribute(k_merge,  cudaFuncAttributeMaxDynamicSharedMemorySize, MRG_SMEM);

    const int TOTV = N_IMG * N_ANCH * 21;
    k_prep<<<(TOTV + 255) / 256, 256>>>(pred);
    k_select<<<N_IMG * N_CLS, 512, SEL_SMEM>>>(pred);
    k_nms<<<N_IMG * N_CLS, 512, NMS_SMEM>>>();
    k_merge<<<N_IMG, 512, MRG_SMEM>>>((float*)d_out);
}